// round 4
// baseline (speedup 1.0000x reference)
#include <cuda_runtime.h>

#define NN 10000
#define EE 320000
#define DD 256
#define NDTOT (NN*DD)

// -------- scratch (static device globals; no allocation) ----------
__device__ float g_q[NDTOT];
__device__ float g_k[NDTOT];
__device__ float g_v[NDTOT];
__device__ float g_s[NDTOT];
__device__ float g_hA[NDTOT];
__device__ float g_hB[NDTOT];
__device__ float g_mean[NDTOT];
__device__ float g_logits[EE];
__device__ int   g_rowptr[NN + 1];
__device__ int   g_srcs[EE];
__device__ int   g_cnt[NN];
__device__ int   g_fill[NN];

// =====================================================================
// Fused QKVS projection: 4 GEMMs [10000,256]x[256,256]+bias sharing A=x
// 128x128 block tile, 8x8 per thread, float4 smem loads.
// grid = (79, 8): blockIdx.y>>1 selects matrix, &1 selects N-half.
// =====================================================================
__global__ void __launch_bounds__(256, 2)
gemm_qkvs(const float* __restrict__ x,
          const float* __restrict__ Wq, const float* __restrict__ bq,
          const float* __restrict__ Wk, const float* __restrict__ bk,
          const float* __restrict__ Wv, const float* __restrict__ bv,
          const float* __restrict__ Ws, const float* __restrict__ bs)
{
    __shared__ float As[16][128];
    __shared__ float Bs[16][128];

    const int tid = threadIdx.x;
    const int tx = tid & 15, ty = tid >> 4;
    const int bm = blockIdx.x * 128;
    const int mat = blockIdx.y >> 1;
    const int bn = (blockIdx.y & 1) * 128;

    const float* B; const float* bias; float* C;
    if      (mat == 0) { B = Wq; bias = bq; C = g_q; }
    else if (mat == 1) { B = Wk; bias = bk; C = g_k; }
    else if (mat == 2) { B = Wv; bias = bv; C = g_v; }
    else               { B = Ws; bias = bs; C = g_s; }

    float acc[8][8];
#pragma unroll
    for (int i = 0; i < 8; i++)
#pragma unroll
        for (int j = 0; j < 8; j++) acc[i][j] = 0.f;

    const int arow = tid & 127;
    const int ak0  = (tid >> 7) * 8;
    const int brow = tid >> 4;
    const int bcol = (tid & 15) * 8;
    const bool avalid = (bm + arow) < NN;
    const float* aptr = x + (size_t)(bm + arow) * DD + ak0;
    const float* bptr = B + (size_t)brow * DD + bn + bcol;

    for (int kt = 0; kt < 256; kt += 16) {
        float4 a0 = make_float4(0.f,0.f,0.f,0.f), a1 = a0;
        if (avalid) {
            a0 = *reinterpret_cast<const float4*>(aptr + kt);
            a1 = *reinterpret_cast<const float4*>(aptr + kt + 4);
        }
        As[ak0+0][arow]=a0.x; As[ak0+1][arow]=a0.y; As[ak0+2][arow]=a0.z; As[ak0+3][arow]=a0.w;
        As[ak0+4][arow]=a1.x; As[ak0+5][arow]=a1.y; As[ak0+6][arow]=a1.z; As[ak0+7][arow]=a1.w;
        float4 b0 = *reinterpret_cast<const float4*>(bptr + (size_t)kt * DD);
        float4 b1 = *reinterpret_cast<const float4*>(bptr + (size_t)kt * DD + 4);
        *reinterpret_cast<float4*>(&Bs[brow][bcol])     = b0;
        *reinterpret_cast<float4*>(&Bs[brow][bcol + 4]) = b1;
        __syncthreads();
#pragma unroll
        for (int kk = 0; kk < 16; kk++) {
            float4 av0 = *reinterpret_cast<const float4*>(&As[kk][ty*8]);
            float4 av1 = *reinterpret_cast<const float4*>(&As[kk][ty*8+4]);
            float4 bv0 = *reinterpret_cast<const float4*>(&Bs[kk][tx*8]);
            float4 bv1 = *reinterpret_cast<const float4*>(&Bs[kk][tx*8+4]);
            float a[8] = {av0.x,av0.y,av0.z,av0.w,av1.x,av1.y,av1.z,av1.w};
            float b[8] = {bv0.x,bv0.y,bv0.z,bv0.w,bv1.x,bv1.y,bv1.z,bv1.w};
#pragma unroll
            for (int i = 0; i < 8; i++)
#pragma unroll
                for (int j = 0; j < 8; j++)
                    acc[i][j] = fmaf(a[i], b[j], acc[i][j]);
        }
        __syncthreads();
    }

    float4 bi0 = *reinterpret_cast<const float4*>(&bias[bn + tx*8]);
    float4 bi1 = *reinterpret_cast<const float4*>(&bias[bn + tx*8 + 4]);
    float bb[8] = {bi0.x,bi0.y,bi0.z,bi0.w,bi1.x,bi1.y,bi1.z,bi1.w};
#pragma unroll
    for (int i = 0; i < 8; i++) {
        int row = bm + ty*8 + i;
        if (row < NN) {
            float4 o0, o1;
            o0.x=acc[i][0]+bb[0]; o0.y=acc[i][1]+bb[1]; o0.z=acc[i][2]+bb[2]; o0.w=acc[i][3]+bb[3];
            o1.x=acc[i][4]+bb[4]; o1.y=acc[i][5]+bb[5]; o1.z=acc[i][6]+bb[6]; o1.w=acc[i][7]+bb[7];
            *reinterpret_cast<float4*>(&C[(size_t)row*DD + bn + tx*8])     = o0;
            *reinterpret_cast<float4*>(&C[(size_t)row*DD + bn + tx*8 + 4]) = o1;
        }
    }
}

// =====================================================================
// Fused SAGE layer: z = mean@Wl + bl + hin@Wr (K=512 virtual concat),
// epilogue: z*BNS*gamma+beta, gated residual with hin, relu -> hout.
// =====================================================================
__global__ void __launch_bounds__(256, 2)
gemm_sage(const float* __restrict__ Wl, const float* __restrict__ bl,
          const float* __restrict__ Wr,
          const float* __restrict__ gamma, const float* __restrict__ beta,
          const float* __restrict__ alpha,
          const float* __restrict__ hin, float* __restrict__ hout)
{
    __shared__ float As[16][128];
    __shared__ float Bs[16][128];

    const int tid = threadIdx.x;
    const int tx = tid & 15, ty = tid >> 4;
    const int bm = blockIdx.x * 128;
    const int bn = blockIdx.y * 128;

    float acc[8][8];
#pragma unroll
    for (int i = 0; i < 8; i++)
#pragma unroll
        for (int j = 0; j < 8; j++) acc[i][j] = 0.f;

    const int arow = tid & 127;
    const int ak0  = (tid >> 7) * 8;
    const int brow = tid >> 4;
    const int bcol = (tid & 15) * 8;
    const bool avalid = (bm + arow) < NN;

    for (int kt = 0; kt < 512; kt += 16) {
        const float* Asrc = (kt < 256) ? g_mean : hin;
        const float* Bsrc = (kt < 256) ? Wl : Wr;
        const int kc = kt & 255;
        float4 a0 = make_float4(0.f,0.f,0.f,0.f), a1 = a0;
        if (avalid) {
            const float* ap = Asrc + (size_t)(bm + arow) * DD + kc + ak0;
            a0 = *reinterpret_cast<const float4*>(ap);
            a1 = *reinterpret_cast<const float4*>(ap + 4);
        }
        As[ak0+0][arow]=a0.x; As[ak0+1][arow]=a0.y; As[ak0+2][arow]=a0.z; As[ak0+3][arow]=a0.w;
        As[ak0+4][arow]=a1.x; As[ak0+5][arow]=a1.y; As[ak0+6][arow]=a1.z; As[ak0+7][arow]=a1.w;
        const float* bp = Bsrc + (size_t)(kc + brow) * DD + bn + bcol;
        float4 b0 = *reinterpret_cast<const float4*>(bp);
        float4 b1 = *reinterpret_cast<const float4*>(bp + 4);
        *reinterpret_cast<float4*>(&Bs[brow][bcol])     = b0;
        *reinterpret_cast<float4*>(&Bs[brow][bcol + 4]) = b1;
        __syncthreads();
#pragma unroll
        for (int kk = 0; kk < 16; kk++) {
            float4 av0 = *reinterpret_cast<const float4*>(&As[kk][ty*8]);
            float4 av1 = *reinterpret_cast<const float4*>(&As[kk][ty*8+4]);
            float4 bv0 = *reinterpret_cast<const float4*>(&Bs[kk][tx*8]);
            float4 bv1 = *reinterpret_cast<const float4*>(&Bs[kk][tx*8+4]);
            float a[8] = {av0.x,av0.y,av0.z,av0.w,av1.x,av1.y,av1.z,av1.w};
            float b[8] = {bv0.x,bv0.y,bv0.z,bv0.w,bv1.x,bv1.y,bv1.z,bv1.w};
#pragma unroll
            for (int i = 0; i < 8; i++)
#pragma unroll
                for (int j = 0; j < 8; j++)
                    acc[i][j] = fmaf(a[i], b[j], acc[i][j]);
        }
        __syncthreads();
    }

    // epilogue: bias + BN(eval) + gated residual + relu
    const float al  = 1.f / (1.f + __expf(-alpha[0]));
    const float oma = 1.f - al;
    const float BNS = 0.9999950000374994f;   // 1/sqrt(1+1e-5)
    const int col0 = bn + tx*8;
    float4 bl0 = *reinterpret_cast<const float4*>(&bl[col0]);
    float4 bl1 = *reinterpret_cast<const float4*>(&bl[col0 + 4]);
    float4 g0  = *reinterpret_cast<const float4*>(&gamma[col0]);
    float4 g1  = *reinterpret_cast<const float4*>(&gamma[col0 + 4]);
    float4 be0 = *reinterpret_cast<const float4*>(&beta[col0]);
    float4 be1 = *reinterpret_cast<const float4*>(&beta[col0 + 4]);
    float blv[8] = {bl0.x,bl0.y,bl0.z,bl0.w,bl1.x,bl1.y,bl1.z,bl1.w};
    float gv[8]  = {g0.x,g0.y,g0.z,g0.w,g1.x,g1.y,g1.z,g1.w};
    float bev[8] = {be0.x,be0.y,be0.z,be0.w,be1.x,be1.y,be1.z,be1.w};

#pragma unroll
    for (int i = 0; i < 8; i++) {
        int row = bm + ty*8 + i;
        if (row < NN) {
            float4 r0 = *reinterpret_cast<const float4*>(&hin[(size_t)row*DD + col0]);
            float4 r1 = *reinterpret_cast<const float4*>(&hin[(size_t)row*DD + col0 + 4]);
            float rv[8] = {r0.x,r0.y,r0.z,r0.w,r1.x,r1.y,r1.z,r1.w};
            float o[8];
#pragma unroll
            for (int j = 0; j < 8; j++) {
                float zz = fmaf((acc[i][j] + blv[j]) * BNS, gv[j], bev[j]);
                o[j] = fmaxf(fmaf(al, zz, oma * rv[j]), 0.f);
            }
            float4 o0 = make_float4(o[0],o[1],o[2],o[3]);
            float4 o1 = make_float4(o[4],o[5],o[6],o[7]);
            *reinterpret_cast<float4*>(&hout[(size_t)row*DD + col0])     = o0;
            *reinterpret_cast<float4*>(&hout[(size_t)row*DD + col0 + 4]) = o1;
        }
    }
}

// -------- CSR build ----------
__global__ void zero_cnt_kernel()
{
    int i = blockIdx.x * blockDim.x + threadIdx.x;
    if (i < NN) g_cnt[i] = 0;
}

__global__ void hist_kernel(const int* __restrict__ ei)
{
    int e = blockIdx.x * blockDim.x + threadIdx.x;
    if (e >= EE) return;
    atomicAdd(&g_cnt[ei[EE + e]], 1);
}

__global__ void scan_kernel()
{
    __shared__ int sh[1024];
    __shared__ int carry;
    int tid = threadIdx.x;
    if (tid == 0) { carry = 0; g_rowptr[0] = 0; }
    __syncthreads();
    for (int base = 0; base < NN; base += 1024) {
        int i = base + tid;
        int v = (i < NN) ? g_cnt[i] : 0;
        sh[tid] = v;
        __syncthreads();
        for (int off = 1; off < 1024; off <<= 1) {
            int t = (tid >= off) ? sh[tid - off] : 0;
            __syncthreads();
            sh[tid] += t;
            __syncthreads();
        }
        int incl = sh[tid] + carry;
        if (i < NN) {
            g_rowptr[i + 1] = incl;
            g_fill[i] = incl - v;   // exclusive
        }
        __syncthreads();
        if (tid == 1023) carry = incl;
        __syncthreads();
    }
}

__global__ void scatter_kernel(const int* __restrict__ ei)
{
    int e = blockIdx.x * blockDim.x + threadIdx.x;
    if (e >= EE) return;
    int src = ei[e];
    int dst = ei[EE + e];
    int pos = atomicAdd(&g_fill[dst], 1);
    g_srcs[pos] = src;
}

// -------- TransformerConv: warp per node, 2-pass softmax aggregation ----------
__global__ void attn_kernel()
{
    int gw = (blockIdx.x * blockDim.x + threadIdx.x) >> 5;
    int lane = threadIdx.x & 31;
    if (gw >= NN) return;
    int beg = g_rowptr[gw], end = g_rowptr[gw + 1];

    float qr[8];
#pragma unroll
    for (int r = 0; r < 8; r++) qr[r] = g_q[(size_t)gw * DD + r * 32 + lane];

    float m = -1e30f;
    for (int e = beg; e < end; e++) {
        int src = g_srcs[e];
        const float* kp = &g_k[(size_t)src * DD];
        float p = 0.f;
#pragma unroll
        for (int r = 0; r < 8; r++) p = fmaf(qr[r], kp[r * 32 + lane], p);
#pragma unroll
        for (int off = 16; off; off >>= 1) p += __shfl_xor_sync(0xffffffffu, p, off);
        p *= 0.0625f;                 // / sqrt(256)
        if (lane == 0) g_logits[e] = p;
        m = fmaxf(m, p);
    }

    float acc[8];
#pragma unroll
    for (int r = 0; r < 8; r++) acc[r] = 0.f;
    float ssum = 0.f;
    for (int e = beg; e < end; e++) {
        int src = g_srcs[e];
        float w = __expf(g_logits[e] - m);
        ssum += w;
        const float* vp = &g_v[(size_t)src * DD];
#pragma unroll
        for (int r = 0; r < 8; r++) acc[r] = fmaf(w, vp[r * 32 + lane], acc[r]);
    }

    float inv = (end > beg) ? (1.f / ssum) : 0.f;
#pragma unroll
    for (int r = 0; r < 8; r++) {
        float val = acc[r] * inv + g_s[(size_t)gw * DD + r * 32 + lane];
        g_hA[(size_t)gw * DD + r * 32 + lane] = fmaxf(val, 0.f);
    }
}

// -------- SAGE mean aggregation: warp per node ----------
__global__ void mean_kernel(const float* __restrict__ h)
{
    int gw = (blockIdx.x * blockDim.x + threadIdx.x) >> 5;
    int lane = threadIdx.x & 31;
    if (gw >= NN) return;
    int beg = g_rowptr[gw], end = g_rowptr[gw + 1];

    float acc[8];
#pragma unroll
    for (int r = 0; r < 8; r++) acc[r] = 0.f;
    for (int e = beg; e < end; e++) {
        int src = g_srcs[e];
        const float* hp = &h[(size_t)src * DD];
#pragma unroll
        for (int r = 0; r < 8; r++) acc[r] += hp[r * 32 + lane];
    }
    int deg = end - beg;
    float inv = 1.f / (float)(deg > 0 ? deg : 1);
#pragma unroll
    for (int r = 0; r < 8; r++)
        g_mean[(size_t)gw * DD + r * 32 + lane] = acc[r] * inv;
}

// -------- launch ----------
extern "C" void kernel_launch(void* const* d_in, const int* in_sizes, int n_in,
                              void* d_out, int out_size)
{
    const float* x     = (const float*)d_in[0];
    const int*   ei    = (const int*)d_in[1];       // int32 (jax x64 disabled)
    const float* Wq    = (const float*)d_in[2];
    const float* bq    = (const float*)d_in[3];
    const float* Wk    = (const float*)d_in[4];
    const float* bk    = (const float*)d_in[5];
    const float* Wv    = (const float*)d_in[6];
    const float* bv    = (const float*)d_in[7];
    const float* Ws    = (const float*)d_in[8];
    const float* bs    = (const float*)d_in[9];
    const float* Wl    = (const float*)d_in[10];
    const float* bl    = (const float*)d_in[11];
    const float* Wr    = (const float*)d_in[12];
    const float* gamma = (const float*)d_in[13];
    const float* beta  = (const float*)d_in[14];
    const float* alpha = (const float*)d_in[15];
    float*       out   = (float*)d_out;

    float *hA, *hB;
    cudaGetSymbolAddress((void**)&hA, g_hA);
    cudaGetSymbolAddress((void**)&hB, g_hB);

    const int MT = (NN + 127) / 128;   // 79

    // CSR build (independent of projections; launch first for overlap-free order)
    zero_cnt_kernel<<<(NN + 255) / 256, 256>>>();
    hist_kernel<<<(EE + 255) / 256, 256>>>(ei);
    scan_kernel<<<1, 1024>>>();
    scatter_kernel<<<(EE + 255) / 256, 256>>>(ei);

    // fused projections
    gemm_qkvs<<<dim3(MT, 8), 256>>>(x, Wq, bq, Wk, bk, Wv, bv, Ws, bs);

    // TransformerConv
    attn_kernel<<<(NN * 32 + 255) / 256, 256>>>();

    // 3 fused SAGE layers
    float* hin = hA;
    for (int l = 0; l < 3; l++) {
        mean_kernel<<<(NN * 32 + 255) / 256, 256>>>(hin);
        float* hout = (l == 2) ? out : ((l == 0) ? hB : hA);
        gemm_sage<<<dim3(MT, 2), 256>>>(Wl + (size_t)l * 65536, bl + (size_t)l * 256,
                                        Wr + (size_t)l * 65536,
                                        gamma + (size_t)l * 256, beta + (size_t)l * 256,
                                        alpha, hin, hout);
        hin = hout;
    }
}

// round 5
// speedup vs baseline: 1.9990x; 1.9990x over previous
#include <cuda_runtime.h>
#include <cstdint>

#define NN 10000
#define EE 320000
#define DD 256
#define NDTOT (NN*DD)

// -------- scratch (static device globals; no allocation) ----------
__device__ float g_q[NDTOT];
__device__ float g_k[NDTOT];
__device__ float g_v[NDTOT];
__device__ float g_s[NDTOT];
__device__ float g_hA[NDTOT];
__device__ float g_hB[NDTOT];
__device__ float g_mean[NDTOT];
__device__ float g_logits[EE];
__device__ int   g_rowptr[NN + 1];
__device__ int   g_srcs[EE];
__device__ int   g_cnt[NN];
__device__ int   g_fill[NN];

// -------- tf32 helpers ----------
__device__ __forceinline__ uint32_t f2tf32(float f)
{
    uint32_t u;
    asm("cvt.rna.tf32.f32 %0, %1;" : "=r"(u) : "f"(f));
    return u;
}

__device__ __forceinline__ void mma_tf32(float* c, const uint32_t* a, const uint32_t* b)
{
    asm volatile(
        "mma.sync.aligned.m16n8k8.row.col.f32.tf32.tf32.f32 "
        "{%0,%1,%2,%3}, {%4,%5,%6,%7}, {%8,%9}, {%0,%1,%2,%3};"
        : "+f"(c[0]), "+f"(c[1]), "+f"(c[2]), "+f"(c[3])
        : "r"(a[0]), "r"(a[1]), "r"(a[2]), "r"(a[3]), "r"(b[0]), "r"(b[1]));
}

#define APAD 36
#define BPAD 136

// =====================================================================
// TF32 MMA GEMM core macros: block 128x128, 8 warps (2x4), warp 64x32.
// As[128][36] (tf32 bits), Bs[32][136]. K chunk = 32.
// =====================================================================

// load a 128x32 A chunk (rows bm.., cols kt..) with NN guard + tf32 cvt
#define LOAD_A_CHUNK(Asrc, kt)                                                  \
    {                                                                           \
        _Pragma("unroll")                                                       \
        for (int i = 0; i < 4; i++) {                                           \
            int idx = i * 256 + tid;            /* 0..1023 */                   \
            int r = idx >> 3, cq = (idx & 7) * 4;                               \
            float4 v = make_float4(0.f, 0.f, 0.f, 0.f);                         \
            int grow = bm + r;                                                  \
            if (grow < NN)                                                      \
                v = *reinterpret_cast<const float4*>(&(Asrc)[(size_t)grow * DD + (kt) + cq]); \
            float4 o;                                                           \
            o.x = __uint_as_float(f2tf32(v.x));                                 \
            o.y = __uint_as_float(f2tf32(v.y));                                 \
            o.z = __uint_as_float(f2tf32(v.z));                                 \
            o.w = __uint_as_float(f2tf32(v.w));                                 \
            *reinterpret_cast<float4*>(&As[r][cq]) = o;                         \
        }                                                                       \
    }

// load a 32x128 B chunk (rows kt.., cols bn..) + tf32 cvt
#define LOAD_B_CHUNK(Bsrc, kt)                                                  \
    {                                                                           \
        _Pragma("unroll")                                                       \
        for (int i = 0; i < 4; i++) {                                           \
            int idx = i * 256 + tid;                                            \
            int r = idx >> 5, cq = (idx & 31) * 4;                              \
            float4 v = *reinterpret_cast<const float4*>(&(Bsrc)[(size_t)((kt) + r) * DD + bn + cq]); \
            float4 o;                                                           \
            o.x = __uint_as_float(f2tf32(v.x));                                 \
            o.y = __uint_as_float(f2tf32(v.y));                                 \
            o.z = __uint_as_float(f2tf32(v.z));                                 \
            o.w = __uint_as_float(f2tf32(v.w));                                 \
            *reinterpret_cast<float4*>(&Bs[r][cq]) = o;                         \
        }                                                                       \
    }

#define COMPUTE_CHUNK()                                                         \
    {                                                                           \
        _Pragma("unroll")                                                       \
        for (int k8 = 0; k8 < 4; k8++) {                                        \
            const int kb = k8 * 8;                                              \
            uint32_t af[4][4], bf[4][2];                                        \
            _Pragma("unroll")                                                   \
            for (int mt = 0; mt < 4; mt++) {                                    \
                int mr = wm + mt * 16 + fr;                                     \
                af[mt][0] = __float_as_uint(As[mr    ][kb + fc    ]);           \
                af[mt][1] = __float_as_uint(As[mr + 8][kb + fc    ]);           \
                af[mt][2] = __float_as_uint(As[mr    ][kb + fc + 4]);           \
                af[mt][3] = __float_as_uint(As[mr + 8][kb + fc + 4]);           \
            }                                                                   \
            _Pragma("unroll")                                                   \
            for (int nt = 0; nt < 4; nt++) {                                    \
                int nc = wn + nt * 8 + fr;                                      \
                bf[nt][0] = __float_as_uint(Bs[kb + fc    ][nc]);               \
                bf[nt][1] = __float_as_uint(Bs[kb + fc + 4][nc]);               \
            }                                                                   \
            _Pragma("unroll")                                                   \
            for (int mt = 0; mt < 4; mt++)                                      \
                _Pragma("unroll")                                               \
                for (int nt = 0; nt < 4; nt++)                                  \
                    mma_tf32(acc[mt][nt], af[mt], bf[nt]);                      \
        }                                                                       \
    }

// =====================================================================
// Fused QKVS projection (4 GEMMs sharing A = x), grid (79, 8)
// =====================================================================
__global__ void __launch_bounds__(256)
gemm_qkvs(const float* __restrict__ x,
          const float* __restrict__ Wq, const float* __restrict__ bq,
          const float* __restrict__ Wk, const float* __restrict__ bk,
          const float* __restrict__ Wv, const float* __restrict__ bv,
          const float* __restrict__ Ws, const float* __restrict__ bs)
{
    __shared__ float As[128][APAD];
    __shared__ float Bs[32][BPAD];

    const int tid  = threadIdx.x;
    const int lane = tid & 31;
    const int warp = tid >> 5;
    const int wm = (warp >> 2) * 64;   // warp row origin in tile
    const int wn = (warp & 3) * 32;    // warp col origin in tile
    const int fr = lane >> 2;          // fragment row (0..7)
    const int fc = lane & 3;           // fragment col (0..3)
    const int bm = blockIdx.x * 128;
    const int mat = blockIdx.y >> 1;
    const int bn  = (blockIdx.y & 1) * 128;

    const float* B; const float* bias; float* C;
    if      (mat == 0) { B = Wq; bias = bq; C = g_q; }
    else if (mat == 1) { B = Wk; bias = bk; C = g_k; }
    else if (mat == 2) { B = Wv; bias = bv; C = g_v; }
    else               { B = Ws; bias = bs; C = g_s; }

    float acc[4][4][4];
#pragma unroll
    for (int mt = 0; mt < 4; mt++)
#pragma unroll
        for (int nt = 0; nt < 4; nt++)
#pragma unroll
            for (int r = 0; r < 4; r++) acc[mt][nt][r] = 0.f;

    for (int kt = 0; kt < 256; kt += 32) {
        LOAD_A_CHUNK(x, kt);
        LOAD_B_CHUNK(B, kt);
        __syncthreads();
        COMPUTE_CHUNK();
        __syncthreads();
    }

    // epilogue: + bias, store
#pragma unroll
    for (int mt = 0; mt < 4; mt++) {
#pragma unroll
        for (int nt = 0; nt < 4; nt++) {
            int row = bm + wm + mt * 16 + fr;
            int col = bn + wn + nt * 8 + fc * 2;
            float b0 = bias[col], b1 = bias[col + 1];
            if (row < NN) {
                float2 o = make_float2(acc[mt][nt][0] + b0, acc[mt][nt][1] + b1);
                *reinterpret_cast<float2*>(&C[(size_t)row * DD + col]) = o;
            }
            if (row + 8 < NN) {
                float2 o = make_float2(acc[mt][nt][2] + b0, acc[mt][nt][3] + b1);
                *reinterpret_cast<float2*>(&C[(size_t)(row + 8) * DD + col]) = o;
            }
        }
    }
}

// =====================================================================
// Fused SAGE layer: z = mean@Wl + bl + hin@Wr (virtual K=512),
// epilogue: BN(eval) + gated residual + relu. grid (79, 2)
// =====================================================================
__global__ void __launch_bounds__(256)
gemm_sage(const float* __restrict__ Wl, const float* __restrict__ bl,
          const float* __restrict__ Wr,
          const float* __restrict__ gamma, const float* __restrict__ beta,
          const float* __restrict__ alpha,
          const float* __restrict__ hin, float* __restrict__ hout)
{
    __shared__ float As[128][APAD];
    __shared__ float Bs[32][BPAD];

    const int tid  = threadIdx.x;
    const int lane = tid & 31;
    const int warp = tid >> 5;
    const int wm = (warp >> 2) * 64;
    const int wn = (warp & 3) * 32;
    const int fr = lane >> 2;
    const int fc = lane & 3;
    const int bm = blockIdx.x * 128;
    const int bn = blockIdx.y * 128;

    float acc[4][4][4];
#pragma unroll
    for (int mt = 0; mt < 4; mt++)
#pragma unroll
        for (int nt = 0; nt < 4; nt++)
#pragma unroll
            for (int r = 0; r < 4; r++) acc[mt][nt][r] = 0.f;

    for (int kt = 0; kt < 512; kt += 32) {
        if (kt < 256) {
            LOAD_A_CHUNK(g_mean, kt);
            LOAD_B_CHUNK(Wl, kt);
        } else {
            LOAD_A_CHUNK(hin, kt - 256);
            LOAD_B_CHUNK(Wr, kt - 256);
        }
        __syncthreads();
        COMPUTE_CHUNK();
        __syncthreads();
    }

    // epilogue
    const float al  = 1.f / (1.f + __expf(-alpha[0]));
    const float oma = 1.f - al;
    const float BNS = 0.9999950000374994f;   // 1/sqrt(1+1e-5)

#pragma unroll
    for (int mt = 0; mt < 4; mt++) {
#pragma unroll
        for (int nt = 0; nt < 4; nt++) {
            int row = bm + wm + mt * 16 + fr;
            int col = bn + wn + nt * 8 + fc * 2;
            float blv0 = bl[col],    blv1 = bl[col + 1];
            float gv0  = gamma[col], gv1  = gamma[col + 1];
            float bev0 = beta[col],  bev1 = beta[col + 1];
            if (row < NN) {
                float2 rv = *reinterpret_cast<const float2*>(&hin[(size_t)row * DD + col]);
                float z0 = fmaf((acc[mt][nt][0] + blv0) * BNS, gv0, bev0);
                float z1 = fmaf((acc[mt][nt][1] + blv1) * BNS, gv1, bev1);
                float2 o = make_float2(fmaxf(fmaf(al, z0, oma * rv.x), 0.f),
                                       fmaxf(fmaf(al, z1, oma * rv.y), 0.f));
                *reinterpret_cast<float2*>(&hout[(size_t)row * DD + col]) = o;
            }
            if (row + 8 < NN) {
                float2 rv = *reinterpret_cast<const float2*>(&hin[(size_t)(row + 8) * DD + col]);
                float z0 = fmaf((acc[mt][nt][2] + blv0) * BNS, gv0, bev0);
                float z1 = fmaf((acc[mt][nt][3] + blv1) * BNS, gv1, bev1);
                float2 o = make_float2(fmaxf(fmaf(al, z0, oma * rv.x), 0.f),
                                       fmaxf(fmaf(al, z1, oma * rv.y), 0.f));
                *reinterpret_cast<float2*>(&hout[(size_t)(row + 8) * DD + col]) = o;
            }
        }
    }
}

// -------- CSR build ----------
__global__ void zero_cnt_kernel()
{
    int i = blockIdx.x * blockDim.x + threadIdx.x;
    if (i < NN) g_cnt[i] = 0;
}

__global__ void hist_kernel(const int* __restrict__ ei)
{
    int e = blockIdx.x * blockDim.x + threadIdx.x;
    if (e >= EE) return;
    atomicAdd(&g_cnt[ei[EE + e]], 1);
}

__global__ void scan_kernel()
{
    __shared__ int sh[1024];
    __shared__ int carry;
    int tid = threadIdx.x;
    if (tid == 0) { carry = 0; g_rowptr[0] = 0; }
    __syncthreads();
    for (int base = 0; base < NN; base += 1024) {
        int i = base + tid;
        int v = (i < NN) ? g_cnt[i] : 0;
        sh[tid] = v;
        __syncthreads();
        for (int off = 1; off < 1024; off <<= 1) {
            int t = (tid >= off) ? sh[tid - off] : 0;
            __syncthreads();
            sh[tid] += t;
            __syncthreads();
        }
        int incl = sh[tid] + carry;
        if (i < NN) {
            g_rowptr[i + 1] = incl;
            g_fill[i] = incl - v;   // exclusive
        }
        __syncthreads();
        if (tid == 1023) carry = incl;
        __syncthreads();
    }
}

__global__ void scatter_kernel(const int* __restrict__ ei)
{
    int e = blockIdx.x * blockDim.x + threadIdx.x;
    if (e >= EE) return;
    int src = ei[e];
    int dst = ei[EE + e];
    int pos = atomicAdd(&g_fill[dst], 1);
    g_srcs[pos] = src;
}

// -------- TransformerConv: warp per node, 2-pass softmax aggregation ----------
__global__ void attn_kernel()
{
    int gw = (blockIdx.x * blockDim.x + threadIdx.x) >> 5;
    int lane = threadIdx.x & 31;
    if (gw >= NN) return;
    int beg = g_rowptr[gw], end = g_rowptr[gw + 1];

    float qr[8];
#pragma unroll
    for (int r = 0; r < 8; r++) qr[r] = g_q[(size_t)gw * DD + r * 32 + lane];

    float m = -1e30f;
    for (int e = beg; e < end; e++) {
        int src = g_srcs[e];
        const float* kp = &g_k[(size_t)src * DD];
        float p = 0.f;
#pragma unroll
        for (int r = 0; r < 8; r++) p = fmaf(qr[r], kp[r * 32 + lane], p);
#pragma unroll
        for (int off = 16; off; off >>= 1) p += __shfl_xor_sync(0xffffffffu, p, off);
        p *= 0.0625f;                 // / sqrt(256)
        if (lane == 0) g_logits[e] = p;
        m = fmaxf(m, p);
    }

    float acc[8];
#pragma unroll
    for (int r = 0; r < 8; r++) acc[r] = 0.f;
    float ssum = 0.f;
    for (int e = beg; e < end; e++) {
        int src = g_srcs[e];
        float w = __expf(g_logits[e] - m);
        ssum += w;
        const float* vp = &g_v[(size_t)src * DD];
#pragma unroll
        for (int r = 0; r < 8; r++) acc[r] = fmaf(w, vp[r * 32 + lane], acc[r]);
    }

    float inv = (end > beg) ? (1.f / ssum) : 0.f;
#pragma unroll
    for (int r = 0; r < 8; r++) {
        float val = acc[r] * inv + g_s[(size_t)gw * DD + r * 32 + lane];
        g_hA[(size_t)gw * DD + r * 32 + lane] = fmaxf(val, 0.f);
    }
}

// -------- SAGE mean aggregation: warp per node ----------
__global__ void mean_kernel(const float* __restrict__ h)
{
    int gw = (blockIdx.x * blockDim.x + threadIdx.x) >> 5;
    int lane = threadIdx.x & 31;
    if (gw >= NN) return;
    int beg = g_rowptr[gw], end = g_rowptr[gw + 1];

    float acc[8];
#pragma unroll
    for (int r = 0; r < 8; r++) acc[r] = 0.f;
    for (int e = beg; e < end; e++) {
        int src = g_srcs[e];
        const float* hp = &h[(size_t)src * DD];
#pragma unroll
        for (int r = 0; r < 8; r++) acc[r] += hp[r * 32 + lane];
    }
    int deg = end - beg;
    float inv = 1.f / (float)(deg > 0 ? deg : 1);
#pragma unroll
    for (int r = 0; r < 8; r++)
        g_mean[(size_t)gw * DD + r * 32 + lane] = acc[r] * inv;
}

// -------- launch ----------
extern "C" void kernel_launch(void* const* d_in, const int* in_sizes, int n_in,
                              void* d_out, int out_size)
{
    const float* x     = (const float*)d_in[0];
    const int*   ei    = (const int*)d_in[1];       // int32 (jax x64 disabled)
    const float* Wq    = (const float*)d_in[2];
    const float* bq    = (const float*)d_in[3];
    const float* Wk    = (const float*)d_in[4];
    const float* bk    = (const float*)d_in[5];
    const float* Wv    = (const float*)d_in[6];
    const float* bv    = (const float*)d_in[7];
    const float* Ws    = (const float*)d_in[8];
    const float* bs    = (const float*)d_in[9];
    const float* Wl    = (const float*)d_in[10];
    const float* bl    = (const float*)d_in[11];
    const float* Wr    = (const float*)d_in[12];
    const float* gamma = (const float*)d_in[13];
    const float* beta  = (const float*)d_in[14];
    const float* alpha = (const float*)d_in[15];
    float*       out   = (float*)d_out;

    float *hA, *hB;
    cudaGetSymbolAddress((void**)&hA, g_hA);
    cudaGetSymbolAddress((void**)&hB, g_hB);

    const int MT = (NN + 127) / 128;   // 79

    // CSR build
    zero_cnt_kernel<<<(NN + 255) / 256, 256>>>();
    hist_kernel<<<(EE + 255) / 256, 256>>>(ei);
    scan_kernel<<<1, 1024>>>();
    scatter_kernel<<<(EE + 255) / 256, 256>>>(ei);

    // fused projections (tf32 tensor cores)
    gemm_qkvs<<<dim3(MT, 8), 256>>>(x, Wq, bq, Wk, bk, Wv, bv, Ws, bs);

    // TransformerConv
    attn_kernel<<<(NN * 32 + 255) / 256, 256>>>();

    // 3 fused SAGE layers
    float* hin = hA;
    for (int l = 0; l < 3; l++) {
        mean_kernel<<<(NN * 32 + 255) / 256, 256>>>(hin);
        float* hout = (l == 2) ? out : ((l == 0) ? hB : hA);
        gemm_sage<<<dim3(MT, 2), 256>>>(Wl + (size_t)l * 65536, bl + (size_t)l * 256,
                                        Wr + (size_t)l * 65536,
                                        gamma + (size_t)l * 256, beta + (size_t)l * 256,
                                        alpha, hin, hout);
        hin = hout;
    }
}